// round 2
// baseline (speedup 1.0000x reference)
#include <cuda_runtime.h>
#include <cuda_bf16.h>

#define R_TOTAL 65536
#define DD 256
#define KK 128
#define TM 64
#define INV_TAU 10.0f

// protoT_g[d][k] : transposed prototypes, filled by pre-kernel
__device__ float protoT_g[DD * KK];

__global__ void transpose_proto_kernel(const float* __restrict__ proto) {
    int t = blockIdx.x * blockDim.x + threadIdx.x;
    if (t < DD * KK) {
        int k = t >> 8;          // t / 256
        int d = t & 255;         // t % 256
        protoT_g[d * KK + k] = proto[k * DD + d];
    }
}

// smem layout (floats):
//   [0, 16384)           phase1: hT [256][64]     | phase2: pT [128][65] (8320 floats)
//   [16384, 49152)       phase1: protoT [256][128]| phase2: proto row-major [128][256]
//   [49152, 49216)       rinv[64]
#define SMEM_FLOATS (16384 + 32768 + 64)

__global__ __launch_bounds__(256) void softcodebook_kernel(
    const float* __restrict__ h,
    const float* __restrict__ proto,
    float* __restrict__ out)
{
    extern __shared__ float smem[];
    float* hT   = smem;             // phase1
    float* pT   = smem;             // phase2 (stride 65)
    float* big  = smem + 16384;     // protoT (p1) / proto (p2)
    float* rinv = smem + 16384 + 32768;

    const int tid = threadIdx.x;
    const int tx = tid & 15;        // 0..15 -> k-cols (x8)
    const int ty = tid >> 4;        // 0..15 -> rows (x4)
    const int row0 = blockIdx.x * TM;

    // ---- load protoT[d][k] into smem (coalesced 128KB copy) ----
    {
        const float4* src = (const float4*)protoT_g;
        float4* dst = (float4*)big;
        #pragma unroll 4
        for (int i = tid; i < 8192; i += 256) dst[i] = src[i];
    }

    // ---- load h tile transposed into hT[d][row] ----
    {
        int r = tid >> 2;           // 0..63 local row
        int q = tid & 3;            // quarter of D
        const float4* hrow = (const float4*)(h + (size_t)(row0 + r) * DD + q * 64);
        #pragma unroll
        for (int it = 0; it < 16; ++it) {
            float4 v = hrow[it];
            int d = q * 64 + it * 4;
            hT[(d + 0) * 64 + r] = v.x;
            hT[(d + 1) * 64 + r] = v.y;
            hT[(d + 2) * 64 + r] = v.z;
            hT[(d + 3) * 64 + r] = v.w;
        }
    }
    __syncthreads();

    // ---- row norms (threads 0..63) ----
    if (tid < 64) {
        float ss = 0.0f;
        #pragma unroll 8
        for (int d = 0; d < DD; ++d) {
            float v = hT[d * 64 + tid];
            ss += v * v;
        }
        float nrm = sqrtf(ss);
        rinv[tid] = 1.0f / fmaxf(nrm, 1e-12f);
    }
    __syncthreads();

    // ---- rescale hT in place: h_bar ----
    #pragma unroll 4
    for (int j = tid; j < 16384; j += 256) {
        hT[j] *= rinv[j & 63];
    }
    __syncthreads();

    // ---- sim GEMM: acc[i][j] = sum_d h_bar[row][d] * protoT[d][k] ----
    float acc[4][8];
    #pragma unroll
    for (int i = 0; i < 4; ++i)
        #pragma unroll
        for (int j = 0; j < 8; ++j) acc[i][j] = 0.0f;

    #pragma unroll 4
    for (int d = 0; d < DD; ++d) {
        float4 a  = *(const float4*)&hT[d * 64 + ty * 4];
        float4 b0 = *(const float4*)&big[d * 128 + tx * 8];
        float4 b1 = *(const float4*)&big[d * 128 + tx * 8 + 4];
        float av[4] = {a.x, a.y, a.z, a.w};
        float bv[8] = {b0.x, b0.y, b0.z, b0.w, b1.x, b1.y, b1.z, b1.w};
        #pragma unroll
        for (int i = 0; i < 4; ++i)
            #pragma unroll
            for (int j = 0; j < 8; ++j)
                acc[i][j] = fmaf(av[i], bv[j], acc[i][j]);
    }

    // ---- softmax over K (16 lanes x 8 local) ----
    float pv[4][8];
    #pragma unroll
    for (int i = 0; i < 4; ++i) {
        float mx = acc[i][0];
        #pragma unroll
        for (int j = 1; j < 8; ++j) mx = fmaxf(mx, acc[i][j]);
        #pragma unroll
        for (int off = 8; off >= 1; off >>= 1)
            mx = fmaxf(mx, __shfl_xor_sync(0xffffffffu, mx, off));
        float sum = 0.0f;
        #pragma unroll
        for (int j = 0; j < 8; ++j) {
            float e = __expf((acc[i][j] - mx) * INV_TAU);
            pv[i][j] = e;
            sum += e;
        }
        #pragma unroll
        for (int off = 8; off >= 1; off >>= 1)
            sum += __shfl_xor_sync(0xffffffffu, sum, off);
        float is = 1.0f / sum;
        #pragma unroll
        for (int j = 0; j < 8; ++j) pv[i][j] *= is;
    }

    // ---- write p to gmem ----
    #pragma unroll
    for (int i = 0; i < 4; ++i) {
        size_t row = (size_t)(row0 + ty * 4 + i);
        float4 v0 = make_float4(pv[i][0], pv[i][1], pv[i][2], pv[i][3]);
        float4 v1 = make_float4(pv[i][4], pv[i][5], pv[i][6], pv[i][7]);
        *(float4*)&out[row * KK + tx * 8]     = v0;
        *(float4*)&out[row * KK + tx * 8 + 4] = v1;
    }

    __syncthreads();   // everyone done reading hT / protoT

    // ---- stage pT[k][m] (stride 65) and row-major proto ----
    #pragma unroll
    for (int i = 0; i < 4; ++i)
        #pragma unroll
        for (int j = 0; j < 8; ++j)
            pT[(tx * 8 + j) * 65 + ty * 4 + i] = pv[i][j];
    {
        const float4* src = (const float4*)proto;
        float4* dst = (float4*)big;
        #pragma unroll 4
        for (int i = tid; i < 8192; i += 256) dst[i] = src[i];
    }
    __syncthreads();

    // ---- z GEMM: z[row][d] = sum_k p[row][k] * proto[k][d]; two d-halves ----
    float* zout = out + (size_t)R_TOTAL * KK;
    #pragma unroll
    for (int half = 0; half < 2; ++half) {
        float zacc[4][8];
        #pragma unroll
        for (int i = 0; i < 4; ++i)
            #pragma unroll
            for (int j = 0; j < 8; ++j) zacc[i][j] = 0.0f;

        #pragma unroll 4
        for (int k = 0; k < KK; ++k) {
            float av[4];
            #pragma unroll
            for (int i = 0; i < 4; ++i) av[i] = pT[k * 65 + ty * 4 + i];
            float4 b0 = *(const float4*)&big[k * 256 + half * 128 + tx * 8];
            float4 b1 = *(const float4*)&big[k * 256 + half * 128 + tx * 8 + 4];
            float bv[8] = {b0.x, b0.y, b0.z, b0.w, b1.x, b1.y, b1.z, b1.w};
            #pragma unroll
            for (int i = 0; i < 4; ++i)
                #pragma unroll
                for (int j = 0; j < 8; ++j)
                    zacc[i][j] = fmaf(av[i], bv[j], zacc[i][j]);
        }

        #pragma unroll
        for (int i = 0; i < 4; ++i) {
            size_t row = (size_t)(row0 + ty * 4 + i);
            float4 v0 = make_float4(zacc[i][0], zacc[i][1], zacc[i][2], zacc[i][3]);
            float4 v1 = make_float4(zacc[i][4], zacc[i][5], zacc[i][6], zacc[i][7]);
            *(float4*)&zout[row * DD + half * 128 + tx * 8]     = v0;
            *(float4*)&zout[row * DD + half * 128 + tx * 8 + 4] = v1;
        }
    }
}

extern "C" void kernel_launch(void* const* d_in, const int* in_sizes, int n_in,
                              void* d_out, int out_size) {
    const float* h     = (const float*)d_in[0];   // (64,1024,256) fp32
    const float* proto = (const float*)d_in[1];   // (128,256) fp32
    float* out = (float*)d_out;                   // p (65536*128) then z (65536*256)

    static int configured = 0;
    // cudaFuncSetAttribute is idempotent & cheap; call unconditionally to stay
    // deterministic across capture/replay.
    cudaFuncSetAttribute(softcodebook_kernel,
                         cudaFuncAttributeMaxDynamicSharedMemorySize,
                         SMEM_FLOATS * sizeof(float));
    (void)configured;

    transpose_proto_kernel<<<(DD * KK + 255) / 256, 256>>>(proto);
    softcodebook_kernel<<<R_TOTAL / TM, 256, SMEM_FLOATS * sizeof(float)>>>(h, proto, out);
}

// round 5
// speedup vs baseline: 2.4076x; 2.4076x over previous
#include <cuda_runtime.h>
#include <cuda_bf16.h>
#include <cstdint>
#include <cstring>

#define RT_TOT 65536
#define BR     256
#define NGRID  (RT_TOT / BR)   // 256 CTAs

// smem map (bytes)
#define SM_R1    0u        // 128KB: sim A frags (per d-half) -> later z B frags
#define SM_R2    131072u   // 64KB : sim B frags (per d-half) -> later p_lo frags
#define SM_RINV  196608u   // 1KB  : rinv[256]
#define SM_BYTES 197632u

// gmem fragment tables (filled by prep kernel)
__device__ uint4 g_simB4[8192];  // [dh2][var2][kt8][nt16][lane32] x 8B
__device__ uint4 g_zB4[8192];    // [var2][kz8][nt32][lane32] x 8B

union BU { __nv_bfloat162 b; uint32_t u; };

__device__ __forceinline__ uint32_t pk_hi(float a, float b) {
    BU t; t.b = __floats2bfloat162_rn(a, b); return t.u;
}
__device__ __forceinline__ void split2(float a, float b, uint32_t& hi, uint32_t& lo) {
    __nv_bfloat16 ha = __float2bfloat16(a), hb = __float2bfloat16(b);
    __nv_bfloat16 la = __float2bfloat16(a - __bfloat162float(ha));
    __nv_bfloat16 lb = __float2bfloat16(b - __bfloat162float(hb));
    BU th, tl;
    th.b = __halves2bfloat162(ha, hb);
    tl.b = __halves2bfloat162(la, lb);
    hi = th.u; lo = tl.u;
}

__global__ void prep_kernel(const float* __restrict__ proto) {
    int id = blockIdx.x * blockDim.x + threadIdx.x;   // 65536 threads
    uint32_t* simB = (uint32_t*)g_simB4;
    uint32_t* zB   = (uint32_t*)g_zB4;
    if (id < 32768) {
        // sim B: contraction k = d, n = codebook c. B[d][c] = proto[c][d]
        int pair = id & 1, lane = (id >> 1) & 31, nt = (id >> 6) & 15;
        int ktl = (id >> 10) & 7, var = (id >> 13) & 1, dh = (id >> 14) & 1;
        int d0 = dh * 128 + ktl * 16 + (lane & 3) * 2 + pair * 8;
        int c  = nt * 8 + (lane >> 2);
        float v0 = proto[c * 256 + d0];
        float v1 = proto[c * 256 + d0 + 1];
        uint32_t hi, lo; split2(v0, v1, hi, lo);
        simB[id] = var ? lo : hi;
    } else {
        // z B: contraction k = codebook c, n = d. B[c][d] = proto[c][d]
        int e = id - 32768;
        int pair = e & 1, lane = (e >> 1) & 31, nt = (e >> 6) & 31;
        int kz = (e >> 11) & 7, var = (e >> 14) & 1;
        int c0 = kz * 16 + (lane & 3) * 2 + pair * 8;
        int d  = nt * 8 + (lane >> 2);
        float v0 = proto[c0 * 256 + d];
        float v1 = proto[(c0 + 1) * 256 + d];
        uint32_t hi, lo; split2(v0, v1, hi, lo);
        zB[e] = var ? lo : hi;
    }
}

#define MMA4(c, a0, a1, a2, a3, b0, b1)                                     \
    asm volatile("mma.sync.aligned.m16n8k16.row.col.f32.bf16.bf16.f32 "     \
        "{%0,%1,%2,%3}, {%4,%5,%6,%7}, {%8,%9}, {%0,%1,%2,%3};"             \
        : "+f"((c)[0]), "+f"((c)[1]), "+f"((c)[2]), "+f"((c)[3])            \
        : "r"(a0), "r"(a1), "r"(a2), "r"(a3), "r"(b0), "r"(b1))

__global__ __launch_bounds__(256, 1) void softcodebook_mma_kernel(
    const float* __restrict__ h, float* __restrict__ out)
{
    extern __shared__ char sc[];
    float* rinv = (float*)(sc + SM_RINV);
    const int tid = threadIdx.x;
    const int w = tid >> 5, lid = tid & 31;
    const int g = lid >> 2, t4 = lid & 3;
    const int row0 = blockIdx.x * BR;

    // ---- row norms: warp w handles rows w, w+8, ... (256 rows) ----
    for (int i = 0; i < 32; ++i) {
        int r = w + i * 8;
        const float4* hp = (const float4*)(h + (size_t)(row0 + r) * 256);
        float4 a = hp[lid], b = hp[lid + 32];
        float ss = a.x*a.x + a.y*a.y + a.z*a.z + a.w*a.w
                 + b.x*b.x + b.y*b.y + b.z*b.z + b.w*b.w;
        #pragma unroll
        for (int o = 16; o >= 1; o >>= 1) ss += __shfl_xor_sync(0xffffffffu, ss, o);
        if (lid == 0) rinv[r] = 1.0f / fmaxf(sqrtf(ss), 1e-12f);
    }
    __syncthreads();

    float rv[2][2];
    #pragma unroll
    for (int rt = 0; rt < 2; ++rt) {
        rv[rt][0] = rinv[w * 32 + rt * 16 + g];
        rv[rt][1] = rinv[w * 32 + rt * 16 + g + 8];
    }

    // sim accumulators: C[rt][nt][4] -> rows (g,g+8), cols nt*8 + t4*2 (+1)
    float C[2][16][4];
    #pragma unroll
    for (int rt = 0; rt < 2; ++rt)
        #pragma unroll
        for (int nt = 0; nt < 16; ++nt)
            #pragma unroll
            for (int j = 0; j < 4; ++j) C[rt][nt][j] = 0.0f;

    #pragma unroll 1
    for (int dh = 0; dh < 2; ++dh) {
        // ---- build A frags (normalized h, hi/lo split), frag-layout smem ----
        #pragma unroll
        for (int rt = 0; rt < 2; ++rt) {
            size_t rA = (size_t)(row0 + w * 32 + rt * 16 + g) * 256;
            size_t rB = rA + 8 * 256;
            #pragma unroll 1
            for (int kt = 0; kt < 8; ++kt) {
                int db = dh * 128 + kt * 16 + t4 * 2;
                float2 v0 = *(const float2*)(h + rA + db);
                float2 v1 = *(const float2*)(h + rB + db);
                float2 v2 = *(const float2*)(h + rA + db + 8);
                float2 v3 = *(const float2*)(h + rB + db + 8);
                float s0 = rv[rt][0], s1 = rv[rt][1];
                uint4 hi4, lo4;
                split2(v0.x * s0, v0.y * s0, hi4.x, lo4.x);
                split2(v1.x * s1, v1.y * s1, hi4.y, lo4.y);
                split2(v2.x * s0, v2.y * s0, hi4.z, lo4.z);
                split2(v3.x * s1, v3.y * s1, hi4.w, lo4.w);
                uint32_t off = (uint32_t)((((w * 2 + rt) * 8 + kt) * 32 + lid) * 16);
                *(uint4*)(sc + off)          = hi4;
                *(uint4*)(sc + off + 65536u) = lo4;
            }
        }
        // ---- copy sim B half (64KB) from gmem frag table ----
        {
            const uint4* src = g_simB4 + dh * 4096;
            uint4* dst = (uint4*)(sc + SM_R2);
            #pragma unroll
            for (int i = 0; i < 16; ++i) dst[tid + 256 * i] = src[tid + 256 * i];
        }
        __syncthreads();

        // ---- sim MMA: 3 passes (hi*hi, lo*hi, hi*lo) ----
        #pragma unroll 1
        for (int pass = 0; pass < 3; ++pass) {
            uint32_t aB = (pass == 1) ? 65536u : 0u;
            uint32_t bB = SM_R2 + ((pass == 2) ? 32768u : 0u);
            #pragma unroll 1
            for (int kt = 0; kt < 8; ++kt) {
                uint4 A0 = *(const uint4*)(sc + aB + (uint32_t)((((w * 2 + 0) * 8 + kt) * 32 + lid) * 16));
                uint4 A1 = *(const uint4*)(sc + aB + (uint32_t)((((w * 2 + 1) * 8 + kt) * 32 + lid) * 16));
                #pragma unroll
                for (int nt = 0; nt < 16; ++nt) {
                    uint2 bv = *(const uint2*)(sc + bB + (uint32_t)(((kt * 16 + nt) * 32 + lid) * 8));
                    MMA4(C[0][nt], A0.x, A0.y, A0.z, A0.w, bv.x, bv.y);
                    MMA4(C[1][nt], A1.x, A1.y, A1.z, A1.w, bv.x, bv.y);
                }
            }
        }
        __syncthreads();
    }

    // ---- softmax over K=128 (quad shfl), write p, pack p hi/lo ----
    uint32_t PH[2][8][4];
    float* pout = out;
    #pragma unroll
    for (int rt = 0; rt < 2; ++rt) {
        float mx0 = -1e30f, mx1 = -1e30f;
        #pragma unroll
        for (int nt = 0; nt < 16; ++nt) {
            mx0 = fmaxf(mx0, fmaxf(C[rt][nt][0], C[rt][nt][1]));
            mx1 = fmaxf(mx1, fmaxf(C[rt][nt][2], C[rt][nt][3]));
        }
        mx0 = fmaxf(mx0, __shfl_xor_sync(0xffffffffu, mx0, 1));
        mx0 = fmaxf(mx0, __shfl_xor_sync(0xffffffffu, mx0, 2));
        mx1 = fmaxf(mx1, __shfl_xor_sync(0xffffffffu, mx1, 1));
        mx1 = fmaxf(mx1, __shfl_xor_sync(0xffffffffu, mx1, 2));
        float s0 = 0.0f, s1 = 0.0f;
        #pragma unroll
        for (int nt = 0; nt < 16; ++nt) {
            C[rt][nt][0] = __expf((C[rt][nt][0] - mx0) * 10.0f); s0 += C[rt][nt][0];
            C[rt][nt][1] = __expf((C[rt][nt][1] - mx0) * 10.0f); s0 += C[rt][nt][1];
            C[rt][nt][2] = __expf((C[rt][nt][2] - mx1) * 10.0f); s1 += C[rt][nt][2];
            C[rt][nt][3] = __expf((C[rt][nt][3] - mx1) * 10.0f); s1 += C[rt][nt][3];
        }
        s0 += __shfl_xor_sync(0xffffffffu, s0, 1);
        s0 += __shfl_xor_sync(0xffffffffu, s0, 2);
        s1 += __shfl_xor_sync(0xffffffffu, s1, 1);
        s1 += __shfl_xor_sync(0xffffffffu, s1, 2);
        float i0 = 1.0f / s0, i1 = 1.0f / s1;
        size_t prow0 = (size_t)(row0 + w * 32 + rt * 16 + g) * 128 + t4 * 2;
        size_t prow1 = prow0 + 8 * 128;
        #pragma unroll
        for (int nt = 0; nt < 16; ++nt) {
            C[rt][nt][0] *= i0; C[rt][nt][1] *= i0;
            C[rt][nt][2] *= i1; C[rt][nt][3] *= i1;
            *(float2*)(pout + prow0 + nt * 8) = make_float2(C[rt][nt][0], C[rt][nt][1]);
            *(float2*)(pout + prow1 + nt * 8) = make_float2(C[rt][nt][2], C[rt][nt][3]);
        }
        // pack p -> z A frags: hi in regs, lo to smem (R2)
        #pragma unroll
        for (int kz = 0; kz < 8; ++kz) {
            uint4 lo4;
            split2(C[rt][2 * kz][0],     C[rt][2 * kz][1],     PH[rt][kz][0], lo4.x);
            split2(C[rt][2 * kz][2],     C[rt][2 * kz][3],     PH[rt][kz][1], lo4.y);
            split2(C[rt][2 * kz + 1][0], C[rt][2 * kz + 1][1], PH[rt][kz][2], lo4.z);
            split2(C[rt][2 * kz + 1][2], C[rt][2 * kz + 1][3], PH[rt][kz][3], lo4.w);
            *(uint4*)(sc + SM_R2 + (uint32_t)((((w * 2 + rt) * 8 + kz) * 32 + lid) * 16)) = lo4;
        }
    }

    // ---- copy z B frags (128KB) into R1 (sim A frags are dead) ----
    {
        uint4* dst = (uint4*)sc;
        #pragma unroll
        for (int i = 0; i < 32; ++i) dst[tid + 256 * i] = g_zB4[tid + 256 * i];
    }
    __syncthreads();

    // ---- z GEMM: A = p (hi regs / lo smem), B = proto frags in R1 ----
    float* zout = out + (size_t)RT_TOT * 128;
    #pragma unroll 1
    for (int dc = 0; dc < 4; ++dc) {
        float Z[2][8][4];
        #pragma unroll
        for (int rt = 0; rt < 2; ++rt)
            #pragma unroll
            for (int nt = 0; nt < 8; ++nt)
                #pragma unroll
                for (int j = 0; j < 4; ++j) Z[rt][nt][j] = 0.0f;

        // passes (hi,hi) and (hi,lo): A from PH registers
        #pragma unroll 1
        for (int pv = 0; pv < 2; ++pv) {
            uint32_t bB = pv ? 65536u : 0u;
            #pragma unroll
            for (int kz = 0; kz < 8; ++kz) {
                #pragma unroll
                for (int nt = 0; nt < 8; ++nt) {
                    uint2 bv = *(const uint2*)(sc + bB + (uint32_t)(((kz * 32 + dc * 8 + nt) * 32 + lid) * 8));
                    MMA4(Z[0][nt], PH[0][kz][0], PH[0][kz][1], PH[0][kz][2], PH[0][kz][3], bv.x, bv.y);
                    MMA4(Z[1][nt], PH[1][kz][0], PH[1][kz][1], PH[1][kz][2], PH[1][kz][3], bv.x, bv.y);
                }
            }
        }
        // pass (lo,hi): A from smem
        #pragma unroll 1
        for (int kz = 0; kz < 8; ++kz) {
            uint4 L0 = *(const uint4*)(sc + SM_R2 + (uint32_t)((((w * 2 + 0) * 8 + kz) * 32 + lid) * 16));
            uint4 L1 = *(const uint4*)(sc + SM_R2 + (uint32_t)((((w * 2 + 1) * 8 + kz) * 32 + lid) * 16));
            #pragma unroll
            for (int nt = 0; nt < 8; ++nt) {
                uint2 bv = *(const uint2*)(sc + (uint32_t)(((kz * 32 + dc * 8 + nt) * 32 + lid) * 8));
                MMA4(Z[0][nt], L0.x, L0.y, L0.z, L0.w, bv.x, bv.y);
                MMA4(Z[1][nt], L1.x, L1.y, L1.z, L1.w, bv.x, bv.y);
            }
        }
        // store z chunk
        #pragma unroll
        for (int rt = 0; rt < 2; ++rt) {
            size_t zr0 = (size_t)(row0 + w * 32 + rt * 16 + g) * 256 + dc * 64 + t4 * 2;
            size_t zr1 = zr0 + 8 * 256;
            #pragma unroll
            for (int nt = 0; nt < 8; ++nt) {
                *(float2*)(zout + zr0 + nt * 8) = make_float2(Z[rt][nt][0], Z[rt][nt][1]);
                *(float2*)(zout + zr1 + nt * 8) = make_float2(Z[rt][nt][2], Z[rt][nt][3]);
            }
        }
    }
}

extern "C" void kernel_launch(void* const* d_in, const int* in_sizes, int n_in,
                              void* d_out, int out_size) {
    const float* h     = (const float*)d_in[0];   // (64,1024,256) fp32
    const float* proto = (const float*)d_in[1];   // (128,256) fp32
    float* out = (float*)d_out;                   // p (65536*128) ++ z (65536*256)

    cudaFuncSetAttribute(softcodebook_mma_kernel,
                         cudaFuncAttributeMaxDynamicSharedMemorySize, SM_BYTES);

    prep_kernel<<<256, 256>>>(proto);
    softcodebook_mma_kernel<<<NGRID, 256, SM_BYTES>>>(h, out);
}

// round 7
// speedup vs baseline: 2.8389x; 1.1791x over previous
#include <cuda_runtime.h>
#include <cuda_bf16.h>
#include <cstdint>
#include <cstring>

#define RT_TOT 65536
#define BR     256
#define NTHR   512
#define NGRID  (RT_TOT / BR)   // 256 CTAs

// smem map (bytes)
// phase1: A_hi [0,64K) + A_lo [64K,128K) + simB [128K,192K)
// phase2: zB   [0,128K)                + p_lo [128K,192K)
#define SM_R2    131072u
#define SM_RINV  196608u   // 1KB: rinv[256]
#define SM_BYTES 197632u

// gmem fragment tables (filled by prep kernel)
__device__ uint4 g_simB4[8192];  // [dh2][var2][kt8][nt16][lane32] x 16B
__device__ uint4 g_zB4[8192];    // [var2][kz8][nt32][lane32] x 16B

union BU { __nv_bfloat162 b; uint32_t u; };

__device__ __forceinline__ void split2(float a, float b, uint32_t& hi, uint32_t& lo) {
    __nv_bfloat16 ha = __float2bfloat16(a), hb = __float2bfloat16(b);
    __nv_bfloat16 la = __float2bfloat16(a - __bfloat162float(ha));
    __nv_bfloat16 lb = __float2bfloat16(b - __bfloat162float(hb));
    BU th, tl;
    th.b = __halves2bfloat162(ha, hb);
    tl.b = __halves2bfloat162(la, lb);
    hi = th.u; lo = tl.u;
}

__global__ void prep_kernel(const float* __restrict__ proto) {
    int id = blockIdx.x * blockDim.x + threadIdx.x;   // 65536 threads
    uint32_t* simB = (uint32_t*)g_simB4;
    uint32_t* zB   = (uint32_t*)g_zB4;
    if (id < 32768) {
        // sim B: contraction k = d, n = codebook c. B[d][c] = proto[c][d]
        int pair = id & 1, lane = (id >> 1) & 31, nt = (id >> 6) & 15;
        int ktl = (id >> 10) & 7, var = (id >> 13) & 1, dh = (id >> 14) & 1;
        int d0 = dh * 128 + ktl * 16 + (lane & 3) * 2 + pair * 8;
        int c  = nt * 8 + (lane >> 2);
        float v0 = proto[c * 256 + d0];
        float v1 = proto[c * 256 + d0 + 1];
        uint32_t hi, lo; split2(v0, v1, hi, lo);
        simB[id] = var ? lo : hi;
    } else {
        // z B: contraction k = codebook c, n = d. B[c][d] = proto[c][d]
        int e = id - 32768;
        int pair = e & 1, lane = (e >> 1) & 31, nt = (e >> 6) & 31;
        int kz = (e >> 11) & 7, var = (e >> 14) & 1;
        int c0 = kz * 16 + (lane & 3) * 2 + pair * 8;
        int d  = nt * 8 + (lane >> 2);
        float v0 = proto[c0 * 256 + d];
        float v1 = proto[(c0 + 1) * 256 + d];
        uint32_t hi, lo; split2(v0, v1, hi, lo);
        zB[e] = var ? lo : hi;
    }
}

#define MMA4(c, a0, a1, a2, a3, b0, b1)                                     \
    asm volatile("mma.sync.aligned.m16n8k16.row.col.f32.bf16.bf16.f32 "     \
        "{%0,%1,%2,%3}, {%4,%5,%6,%7}, {%8,%9}, {%0,%1,%2,%3};"             \
        : "+f"((c)[0]), "+f"((c)[1]), "+f"((c)[2]), "+f"((c)[3])            \
        : "r"(a0), "r"(a1), "r"(a2), "r"(a3), "r"(b0), "r"(b1))

__global__ __launch_bounds__(NTHR, 1) void softcodebook_mma_kernel(
    const float* __restrict__ h, float* __restrict__ out)
{
    extern __shared__ char sc[];
    float* rinv = (float*)(sc + SM_RINV);
    const int tid = threadIdx.x;
    const int w = tid >> 5, lid = tid & 31;     // 16 warps
    const int g = lid >> 2, t4 = lid & 3;
    const int row0 = blockIdx.x * BR;

    // ---- row norms: warp w handles rows w, w+16, ... (256 rows) ----
    #pragma unroll 1
    for (int i = 0; i < 16; ++i) {
        int r = w + i * 16;
        const float4* hp = (const float4*)(h + (size_t)(row0 + r) * 256);
        float4 a = hp[lid], b = hp[lid + 32];
        float ss = a.x*a.x + a.y*a.y + a.z*a.z + a.w*a.w
                 + b.x*b.x + b.y*b.y + b.z*b.z + b.w*b.w;
        #pragma unroll
        for (int o = 16; o >= 1; o >>= 1) ss += __shfl_xor_sync(0xffffffffu, ss, o);
        if (lid == 0) rinv[r] = 1.0f / fmaxf(sqrtf(ss), 1e-12f);
    }
    __syncthreads();

    const float s0r = rinv[w * 16 + g];
    const float s1r = rinv[w * 16 + g + 8];

    // sim accumulators: C[nt][4] -> rows (g, g+8), cols nt*8 + t4*2 (+1)
    float C[16][4];
    #pragma unroll
    for (int nt = 0; nt < 16; ++nt)
        #pragma unroll
        for (int j = 0; j < 4; ++j) C[nt][j] = 0.0f;

    #pragma unroll 1
    for (int dh = 0; dh < 2; ++dh) {
        // ---- build this warp's A frags (normalized h, hi/lo split) ----
        {
            size_t rA = (size_t)(row0 + w * 16 + g) * 256;
            size_t rB = rA + 8 * 256;
            #pragma unroll 1
            for (int kt = 0; kt < 8; ++kt) {
                int db = dh * 128 + kt * 16 + t4 * 2;
                float2 v0 = *(const float2*)(h + rA + db);
                float2 v1 = *(const float2*)(h + rB + db);
                float2 v2 = *(const float2*)(h + rA + db + 8);
                float2 v3 = *(const float2*)(h + rB + db + 8);
                uint4 hi4, lo4;
                split2(v0.x * s0r, v0.y * s0r, hi4.x, lo4.x);
                split2(v1.x * s1r, v1.y * s1r, hi4.y, lo4.y);
                split2(v2.x * s0r, v2.y * s0r, hi4.z, lo4.z);
                split2(v3.x * s1r, v3.y * s1r, hi4.w, lo4.w);
                uint32_t off = (uint32_t)(((w * 8 + kt) * 32 + lid) * 16);
                *(uint4*)(sc + off)          = hi4;
                *(uint4*)(sc + off + 65536u) = lo4;
            }
        }
        // ---- copy sim B half (64KB) from gmem frag table ----
        {
            const uint4* src = g_simB4 + dh * 4096;
            uint4* dst = (uint4*)(sc + SM_R2);
            #pragma unroll
            for (int i = 0; i < 8; ++i) dst[tid + NTHR * i] = src[tid + NTHR * i];
        }
        __syncthreads();

        // ---- sim MMA: 3 passes (hi*hi, lo*hi, hi*lo) ----
        #pragma unroll 1
        for (int pass = 0; pass < 3; ++pass) {
            uint32_t aB = (pass == 1) ? 65536u : 0u;
            uint32_t bB = SM_R2 + ((pass == 2) ? 32768u : 0u);
            #pragma unroll 1
            for (int kt = 0; kt < 8; ++kt) {
                uint4 A0 = *(const uint4*)(sc + aB + (uint32_t)(((w * 8 + kt) * 32 + lid) * 16));
                #pragma unroll
                for (int nt = 0; nt < 16; ++nt) {
                    uint2 bv = *(const uint2*)(sc + bB + (uint32_t)(((kt * 16 + nt) * 32 + lid) * 8));
                    MMA4(C[nt], A0.x, A0.y, A0.z, A0.w, bv.x, bv.y);
                }
            }
        }
        __syncthreads();
    }

    // ---- softmax over K=128 (quad shfl), write p, pack p hi/lo ----
    uint32_t PH[8][4];
    float* pout = out;
    {
        float mx0 = -1e30f, mx1 = -1e30f;
        #pragma unroll
        for (int nt = 0; nt < 16; ++nt) {
            mx0 = fmaxf(mx0, fmaxf(C[nt][0], C[nt][1]));
            mx1 = fmaxf(mx1, fmaxf(C[nt][2], C[nt][3]));
        }
        mx0 = fmaxf(mx0, __shfl_xor_sync(0xffffffffu, mx0, 1));
        mx0 = fmaxf(mx0, __shfl_xor_sync(0xffffffffu, mx0, 2));
        mx1 = fmaxf(mx1, __shfl_xor_sync(0xffffffffu, mx1, 1));
        mx1 = fmaxf(mx1, __shfl_xor_sync(0xffffffffu, mx1, 2));
        float s0 = 0.0f, s1 = 0.0f;
        #pragma unroll
        for (int nt = 0; nt < 16; ++nt) {
            C[nt][0] = __expf((C[nt][0] - mx0) * 10.0f); s0 += C[nt][0];
            C[nt][1] = __expf((C[nt][1] - mx0) * 10.0f); s0 += C[nt][1];
            C[nt][2] = __expf((C[nt][2] - mx1) * 10.0f); s1 += C[nt][2];
            C[nt][3] = __expf((C[nt][3] - mx1) * 10.0f); s1 += C[nt][3];
        }
        s0 += __shfl_xor_sync(0xffffffffu, s0, 1);
        s0 += __shfl_xor_sync(0xffffffffu, s0, 2);
        s1 += __shfl_xor_sync(0xffffffffu, s1, 1);
        s1 += __shfl_xor_sync(0xffffffffu, s1, 2);
        float i0 = 1.0f / s0, i1 = 1.0f / s1;
        size_t prow0 = (size_t)(row0 + w * 16 + g) * 128 + t4 * 2;
        size_t prow1 = prow0 + 8 * 128;
        #pragma unroll
        for (int nt = 0; nt < 16; ++nt) {
            C[nt][0] *= i0; C[nt][1] *= i0;
            C[nt][2] *= i1; C[nt][3] *= i1;
            *(float2*)(pout + prow0 + nt * 8) = make_float2(C[nt][0], C[nt][1]);
            *(float2*)(pout + prow1 + nt * 8) = make_float2(C[nt][2], C[nt][3]);
        }
        // pack p -> z A frags: hi in regs, lo to smem (R2)
        #pragma unroll
        for (int kz = 0; kz < 8; ++kz) {
            uint4 lo4;
            split2(C[2 * kz][0],     C[2 * kz][1],     PH[kz][0], lo4.x);
            split2(C[2 * kz][2],     C[2 * kz][3],     PH[kz][1], lo4.y);
            split2(C[2 * kz + 1][0], C[2 * kz + 1][1], PH[kz][2], lo4.z);
            split2(C[2 * kz + 1][2], C[2 * kz + 1][3], PH[kz][3], lo4.w);
            *(uint4*)(sc + SM_R2 + (uint32_t)(((w * 8 + kz) * 32 + lid) * 16)) = lo4;
        }
    }

    // ---- copy z B frags (128KB) into [0,128K) (sim A frags dead) ----
    {
        uint4* dst = (uint4*)sc;
        #pragma unroll
        for (int i = 0; i < 16; ++i) dst[tid + NTHR * i] = g_zB4[tid + NTHR * i];
    }
    __syncthreads();

    // ---- z GEMM: A = p (hi regs / lo smem), B = proto frags ----
    float* zout = out + (size_t)RT_TOT * 128;
    #pragma unroll 1
    for (int dc = 0; dc < 4; ++dc) {
        float Z[8][4];
        #pragma unroll
        for (int nt = 0; nt < 8; ++nt)
            #pragma unroll
            for (int j = 0; j < 4; ++j) Z[nt][j] = 0.0f;

        // passes (hi,hi) and (hi,lo): A from PH registers
        #pragma unroll 1
        for (int pv = 0; pv < 2; ++pv) {
            uint32_t bB = pv ? 65536u : 0u;
            #pragma unroll
            for (int kz = 0; kz < 8; ++kz) {
                #pragma unroll
                for (int nt = 0; nt < 8; ++nt) {
                    uint2 bv = *(const uint2*)(sc + bB + (uint32_t)(((kz * 32 + dc * 8 + nt) * 32 + lid) * 8));
                    MMA4(Z[nt], PH[kz][0], PH[kz][1], PH[kz][2], PH[kz][3], bv.x, bv.y);
                }
            }
        }
        // pass (lo,hi): A from smem
        #pragma unroll 1
        for (int kz = 0; kz < 8; ++kz) {
            uint4 L0 = *(const uint4*)(sc + SM_R2 + (uint32_t)(((w * 8 + kz) * 32 + lid) * 16));
            #pragma unroll
            for (int nt = 0; nt < 8; ++nt) {
                uint2 bv = *(const uint2*)(sc + (uint32_t)(((kz * 32 + dc * 8 + nt) * 32 + lid) * 8));
                MMA4(Z[nt], L0.x, L0.y, L0.z, L0.w, bv.x, bv.y);
            }
        }
        // store z chunk
        {
            size_t zr0 = (size_t)(row0 + w * 16 + g) * 256 + dc * 64 + t4 * 2;
            size_t zr1 = zr0 + 8 * 256;
            #pragma unroll
            for (int nt = 0; nt < 8; ++nt) {
                *(float2*)(zout + zr0 + nt * 8) = make_float2(Z[nt][0], Z[nt][1]);
                *(float2*)(zout + zr1 + nt * 8) = make_float2(Z[nt][2], Z[nt][3]);
            }
        }
    }
}

extern "C" void kernel_launch(void* const* d_in, const int* in_sizes, int n_in,
                              void* d_out, int out_size) {
    const float* h     = (const float*)d_in[0];   // (64,1024,256) fp32
    const float* proto = (const float*)d_in[1];   // (128,256) fp32
    float* out = (float*)d_out;                   // p (65536*128) ++ z (65536*256)

    cudaFuncSetAttribute(softcodebook_mma_kernel,
                         cudaFuncAttributeMaxDynamicSharedMemorySize, SM_BYTES);

    prep_kernel<<<256, 256>>>(proto);
    softcodebook_mma_kernel<<<NGRID, NTHR, SM_BYTES>>>(h, out);
}

// round 11
// speedup vs baseline: 2.9539x; 1.0405x over previous
#include <cuda_runtime.h>
#include <cuda_bf16.h>
#include <cstdint>

#define RT_TOT 65536
#define BR     256
#define NTHR   512
#define NGRID  (RT_TOT / BR)   // 256 CTAs

// smem: B frags [0,128K) (simB phase1, zB phase2), rinv at 128K
#define SM_RINV  131072u
#define SM_BYTES 132096u

// interleaved fragment tables: uint4 = {hi_b0, hi_b1, lo_b0, lo_b1}
__device__ uint4 g_simB4[8192];  // [dh2][kt8][nt16][lane32]
__device__ uint4 g_zB4[8192];    // [kz8][nt32][lane32]

union BU { __nv_bfloat162 b; uint32_t u; };

__device__ __forceinline__ void split2(float a, float b, uint32_t& hi, uint32_t& lo) {
    __nv_bfloat16 ha = __float2bfloat16(a), hb = __float2bfloat16(b);
    __nv_bfloat16 la = __float2bfloat16(a - __bfloat162float(ha));
    __nv_bfloat16 lb = __float2bfloat16(b - __bfloat162float(hb));
    BU th, tl;
    th.b = __halves2bfloat162(ha, hb);
    tl.b = __halves2bfloat162(la, lb);
    hi = th.u; lo = tl.u;
}

__global__ void prep_kernel(const float* __restrict__ proto) {
    int id = blockIdx.x * blockDim.x + threadIdx.x;   // 16384 threads
    if (id < 8192) {
        // sim B: k = d (contraction), n = codebook c
        int lane = id & 31, nt = (id >> 5) & 15, kt = (id >> 9) & 7, dh = (id >> 12) & 1;
        int d0 = dh * 128 + kt * 16 + (lane & 3) * 2;
        int c  = nt * 8 + (lane >> 2);
        uint32_t h0, l0, h1, l1;
        split2(proto[c * 256 + d0],     proto[c * 256 + d0 + 1], h0, l0);
        split2(proto[c * 256 + d0 + 8], proto[c * 256 + d0 + 9], h1, l1);
        g_simB4[id] = make_uint4(h0, h1, l0, l1);
    } else {
        // z B: k = codebook c (contraction), n = d
        int e = id - 8192;
        int lane = e & 31, nt = (e >> 5) & 31, kz = (e >> 10) & 7;
        int c0 = kz * 16 + (lane & 3) * 2;
        int d  = nt * 8 + (lane >> 2);
        uint32_t h0, l0, h1, l1;
        split2(proto[c0 * 256 + d],       proto[(c0 + 1) * 256 + d], h0, l0);
        split2(proto[(c0 + 8) * 256 + d], proto[(c0 + 9) * 256 + d], h1, l1);
        g_zB4[e] = make_uint4(h0, h1, l0, l1);
    }
}

#define MMA4(c, a0, a1, a2, a3, b0, b1)                                     \
    asm volatile("mma.sync.aligned.m16n8k16.row.col.f32.bf16.bf16.f32 "     \
        "{%0,%1,%2,%3}, {%4,%5,%6,%7}, {%8,%9}, {%0,%1,%2,%3};"             \
        : "+f"((c)[0]), "+f"((c)[1]), "+f"((c)[2]), "+f"((c)[3])            \
        : "r"(a0), "r"(a1), "r"(a2), "r"(a3), "r"(b0), "r"(b1))

__global__ __launch_bounds__(NTHR, 1) void softcodebook_mma_kernel(
    const float* __restrict__ h, float* __restrict__ out)
{
    extern __shared__ char sc[];
    float* rinv = (float*)(sc + SM_RINV);
    const int tid = threadIdx.x;
    const int w = tid >> 5, lid = tid & 31;     // 16 warps
    const int g = lid >> 2, t4 = lid & 3;
    const int row0 = blockIdx.x * BR;

    // ---- copy sim B frags (128KB) ----
    {
        uint4* dst = (uint4*)sc;
        #pragma unroll
        for (int i = 0; i < 16; ++i) dst[tid + NTHR * i] = g_simB4[tid + NTHR * i];
    }

    // ---- per-warp row norms: warp w owns rows w*16 .. w*16+15 ----
    #pragma unroll 1
    for (int i = 0; i < 16; ++i) {
        int r = w * 16 + i;
        const float4* hp = (const float4*)(h + (size_t)(row0 + r) * 256);
        float4 a = hp[lid], b = hp[lid + 32];
        float ss = a.x*a.x + a.y*a.y + a.z*a.z + a.w*a.w
                 + b.x*b.x + b.y*b.y + b.z*b.z + b.w*b.w;
        #pragma unroll
        for (int o = 16; o >= 1; o >>= 1) ss += __shfl_xor_sync(0xffffffffu, ss, o);
        if (lid == 0) rinv[r] = 1.0f / fmaxf(sqrtf(ss), 1e-12f);
    }
    __syncwarp();
    const float s0r = rinv[w * 16 + g];
    const float s1r = rinv[w * 16 + g + 8];
    __syncthreads();   // simB ready

    // sim accumulators: C[nt][4] -> rows (g, g+8), cols nt*8 + t4*2 (+1)
    float C[16][4];
    #pragma unroll
    for (int nt = 0; nt < 16; ++nt)
        #pragma unroll
        for (int j = 0; j < 4; ++j) C[nt][j] = 0.0f;

    // ---- sim GEMM: A built in registers per kt, 3 fused passes per B load ----
    #pragma unroll 1
    for (int dh = 0; dh < 2; ++dh) {
        const size_t rA = (size_t)(row0 + w * 16 + g) * 256 + dh * 128;
        const size_t rB = rA + 8 * 256;
        #pragma unroll 1
        for (int kt = 0; kt < 8; ++kt) {
            int db = kt * 16 + t4 * 2;
            float2 v0 = *(const float2*)(h + rA + db);
            float2 v1 = *(const float2*)(h + rB + db);
            float2 v2 = *(const float2*)(h + rA + db + 8);
            float2 v3 = *(const float2*)(h + rB + db + 8);
            uint32_t a0, a1, a2, a3, l0, l1, l2, l3;
            split2(v0.x * s0r, v0.y * s0r, a0, l0);
            split2(v1.x * s1r, v1.y * s1r, a1, l1);
            split2(v2.x * s0r, v2.y * s0r, a2, l2);
            split2(v3.x * s1r, v3.y * s1r, a3, l3);
            const uint4* Bp = (const uint4*)sc + ((dh * 8 + kt) * 16) * 32 + lid;
            #pragma unroll
            for (int nt = 0; nt < 16; ++nt) {
                uint4 b = Bp[nt * 32];
                MMA4(C[nt], a0, a1, a2, a3, b.x, b.y);   // hi*hi
                MMA4(C[nt], l0, l1, l2, l3, b.x, b.y);   // lo*hi
                MMA4(C[nt], a0, a1, a2, a3, b.z, b.w);   // hi*lo
            }
        }
    }

    // ---- softmax over K=128 (quad shfl), write p, split to PH/PL regs ----
    uint32_t PH[8][4], PL[8][4];
    {
        float mx0 = -1e30f, mx1 = -1e30f;
        #pragma unroll
        for (int nt = 0; nt < 16; ++nt) {
            mx0 = fmaxf(mx0, fmaxf(C[nt][0], C[nt][1]));
            mx1 = fmaxf(mx1, fmaxf(C[nt][2], C[nt][3]));
        }
        mx0 = fmaxf(mx0, __shfl_xor_sync(0xffffffffu, mx0, 1));
        mx0 = fmaxf(mx0, __shfl_xor_sync(0xffffffffu, mx0, 2));
        mx1 = fmaxf(mx1, __shfl_xor_sync(0xffffffffu, mx1, 1));
        mx1 = fmaxf(mx1, __shfl_xor_sync(0xffffffffu, mx1, 2));
        float s0 = 0.0f, s1 = 0.0f;
        #pragma unroll
        for (int nt = 0; nt < 16; ++nt) {
            C[nt][0] = __expf((C[nt][0] - mx0) * 10.0f); s0 += C[nt][0];
            C[nt][1] = __expf((C[nt][1] - mx0) * 10.0f); s0 += C[nt][1];
            C[nt][2] = __expf((C[nt][2] - mx1) * 10.0f); s1 += C[nt][2];
            C[nt][3] = __expf((C[nt][3] - mx1) * 10.0f); s1 += C[nt][3];
        }
        s0 += __shfl_xor_sync(0xffffffffu, s0, 1);
        s0 += __shfl_xor_sync(0xffffffffu, s0, 2);
        s1 += __shfl_xor_sync(0xffffffffu, s1, 1);
        s1 += __shfl_xor_sync(0xffffffffu, s1, 2);
        float i0 = 1.0f / s0, i1 = 1.0f / s1;
        size_t prow0 = (size_t)(row0 + w * 16 + g) * 128 + t4 * 2;
        size_t prow1 = prow0 + 8 * 128;
        #pragma unroll
        for (int nt = 0; nt < 16; ++nt) {
            C[nt][0] *= i0; C[nt][1] *= i0;
            C[nt][2] *= i1; C[nt][3] *= i1;
            *(float2*)(out + prow0 + nt * 8) = make_float2(C[nt][0], C[nt][1]);
            *(float2*)(out + prow1 + nt * 8) = make_float2(C[nt][2], C[nt][3]);
        }
        #pragma unroll
        for (int kz = 0; kz < 8; ++kz) {
            split2(C[2 * kz][0],     C[2 * kz][1],     PH[kz][0], PL[kz][0]);
            split2(C[2 * kz][2],     C[2 * kz][3],     PH[kz][1], PL[kz][1]);
            split2(C[2 * kz + 1][0], C[2 * kz + 1][1], PH[kz][2], PL[kz][2]);
            split2(C[2 * kz + 1][2], C[2 * kz + 1][3], PH[kz][3], PL[kz][3]);
        }
    }

    // ---- swap B region: simB dead -> zB frags (128KB) ----
    __syncthreads();
    {
        uint4* dst = (uint4*)sc;
        #pragma unroll
        for (int i = 0; i < 16; ++i) dst[tid + NTHR * i] = g_zB4[tid + NTHR * i];
    }
    __syncthreads();

    // ---- z GEMM: A = p (PH/PL regs), B = proto frags, 3 passes per load ----
    float* zout = out + (size_t)RT_TOT * 128;
    #pragma unroll 1
    for (int dc = 0; dc < 4; ++dc) {
        float Z[8][4];
        #pragma unroll
        for (int nt = 0; nt < 8; ++nt)
            #pragma unroll
            for (int j = 0; j < 4; ++j) Z[nt][j] = 0.0f;

        #pragma unroll 1
        for (int kz = 0; kz < 8; ++kz) {
            const uint4* Bp = (const uint4*)sc + (kz * 32 + dc * 8) * 32 + lid;
            #pragma unroll
            for (int nt = 0; nt < 8; ++nt) {
                uint4 b = Bp[nt * 32];
                MMA4(Z[nt], PH[kz][0], PH[kz][1], PH[kz][2], PH[kz][3], b.x, b.y);  // hi*hi
                MMA4(Z[nt], PL[kz][0], PL[kz][1], PL[kz][2], PL[kz][3], b.x, b.y);  // lo*hi
                MMA4(Z[nt], PH[kz][0], PH[kz][1], PH[kz][2], PH[kz][3], b.z, b.w);  // hi*lo
            }
        }
        {
            size_t zr0 = (size_t)(row0 + w * 16 + g) * 256 + dc * 64 + t4 * 2;
            size_t zr1 = zr0 + 8 * 256;
            #pragma unroll
            for (int nt = 0; nt < 8; ++nt) {
                *(float2*)(zout + zr0 + nt * 8) = make_float2(Z[nt][0], Z[nt][1]);
                *(float2*)(zout + zr1 + nt * 8) = make_float2(Z[nt][2], Z[nt][3]);
            }
        }
    }
}

extern "C" void kernel_launch(void* const* d_in, const int* in_sizes, int n_in,
                              void* d_out, int out_size) {
    const float* h     = (const float*)d_in[0];   // (64,1024,256) fp32
    const float* proto = (const float*)d_in[1];   // (128,256) fp32
    float* out = (float*)d_out;                   // p (65536*128) ++ z (65536*256)

    cudaFuncSetAttribute(softcodebook_mma_kernel,
                         cudaFuncAttributeMaxDynamicSharedMemorySize, SM_BYTES);

    prep_kernel<<<64, 256>>>(proto);
    softcodebook_mma_kernel<<<NGRID, NTHR, SM_BYTES>>>(h, out);
}